// round 1
// baseline (speedup 1.0000x reference)
#include <cuda_runtime.h>

#define BN 8
#define SN 2048
#define EN 8
#define NTOK (BN*SN)
#define KSPLIT 4
#define KCHUNK (SN/KSPLIT)   /* 512 keys per split */
#define TK 128               /* key tile in smem */
#define QT 128               /* queries per CTA (= threads) */

/* Scratch (allocation-free rule: device globals) */
__device__ float g_Qf[NTOK * 16];
__device__ float g_Kf[NTOK * 16];
__device__ float g_V [NTOK * 8];
__device__ float g_part[NTOK * KSPLIT * 9];

/* ---------------- Kernel 1: per-token features ----------------
 * qlayer(x, phi)_w = prod_{u<=w} cos(x_u+phi_u)  (w>=1),
 * qlayer_0 = prod_{u=1..7} cos(x_u+phi_u).
 * Similarity features: Phi[m] = prod_{w<4} (bit_w(m) ? sin(q_w/2) : cos(q_w/2)).
 */
__device__ __forceinline__ void qk_features(const float xv[8], const float ph[8],
                                            float out16[16]) {
    float c[8];
#pragma unroll
    for (int u = 0; u < 8; u++) c[u] = __cosf(xv[u] + ph[u]);
    float q1 = c[0] * c[1];
    float q2 = q1 * c[2];
    float q3 = q2 * c[3];
    float q0 = c[1] * c[2] * c[3] * c[4] * c[5] * c[6] * c[7];
    float s0, s1, s2, s3, a0, a1, a2, a3;
    __sincosf(0.5f * q0, &s0, &a0);
    __sincosf(0.5f * q1, &s1, &a1);
    __sincosf(0.5f * q2, &s2, &a2);
    __sincosf(0.5f * q3, &s3, &a3);
    float t01[4] = {a0 * a1, s0 * a1, a0 * s1, s0 * s1};
    float t23[4] = {a2 * a3, s2 * a3, a2 * s3, s2 * s3};
#pragma unroll
    for (int m = 0; m < 16; m++) out16[m] = t01[m & 3] * t23[m >> 2];
}

__global__ void features_kernel(const float* __restrict__ x,
                                const float* __restrict__ phi_q,
                                const float* __restrict__ phi_k,
                                const float* __restrict__ phi_v) {
    int t = blockIdx.x * blockDim.x + threadIdx.x;
    if (t >= NTOK) return;

    float xv[8];
    const float4* xp = reinterpret_cast<const float4*>(x + t * 8);
    float4 xa = xp[0], xb = xp[1];
    xv[0] = xa.x; xv[1] = xa.y; xv[2] = xa.z; xv[3] = xa.w;
    xv[4] = xb.x; xv[5] = xb.y; xv[6] = xb.z; xv[7] = xb.w;

    float pq[8], pk[8], pv[8];
#pragma unroll
    for (int u = 0; u < 8; u++) {
        pq[u] = __ldg(&phi_q[u]);
        pk[u] = __ldg(&phi_k[u]);
        pv[u] = __ldg(&phi_v[u]);
    }

    float fq[16], fk[16];
    qk_features(xv, pq, fq);
    qk_features(xv, pk, fk);

    float4* qo = reinterpret_cast<float4*>(g_Qf + t * 16);
    float4* ko = reinterpret_cast<float4*>(g_Kf + t * 16);
#pragma unroll
    for (int i = 0; i < 4; i++) {
        qo[i] = make_float4(fq[4 * i], fq[4 * i + 1], fq[4 * i + 2], fq[4 * i + 3]);
        ko[i] = make_float4(fk[4 * i], fk[4 * i + 1], fk[4 * i + 2], fk[4 * i + 3]);
    }

    /* V: all 8 qlayer outputs */
    {
        float c[8];
#pragma unroll
        for (int u = 0; u < 8; u++) c[u] = __cosf(xv[u] + pv[u]);
        float v[8];
        v[1] = c[0] * c[1];
#pragma unroll
        for (int w = 2; w < 8; w++) v[w] = v[w - 1] * c[w];
        v[0] = c[1] * c[2] * c[3] * c[4] * c[5] * c[6] * c[7];
        float4* vo = reinterpret_cast<float4*>(g_V + t * 8);
        vo[0] = make_float4(v[0], v[1], v[2], v[3]);
        vo[1] = make_float4(v[4], v[5], v[6], v[7]);
    }
}

/* ---------------- Kernel 2: fused attention partials ----------------
 * sim(i,j) = |Qf_i . Kf_j| in [0,1] -> softmax without max subtraction.
 * Each thread owns one query row; keys split across blockIdx.y (KSPLIT).
 */
__global__ __launch_bounds__(QT) void attn_partial_kernel() {
    __shared__ float4 sK[TK * 4];   /* 128 keys x 16 floats = 8KB */
    __shared__ float4 sV[TK * 2];   /* 128 keys x 8  floats = 4KB */

    const int b  = blockIdx.z;
    const int ks = blockIdx.y;
    const int qi = blockIdx.x * QT + threadIdx.x;

    const float4* qp = reinterpret_cast<const float4*>(g_Qf + (b * SN + qi) * 16);
    const float4 q0 = qp[0], q1 = qp[1], q2 = qp[2], q3 = qp[3];

    float den = 0.f;
    float a0 = 0.f, a1 = 0.f, a2 = 0.f, a3 = 0.f;
    float a4 = 0.f, a5 = 0.f, a6 = 0.f, a7 = 0.f;

    const int kbase = b * SN + ks * KCHUNK;

    for (int t0 = 0; t0 < KCHUNK; t0 += TK) {
        const float4* kg = reinterpret_cast<const float4*>(g_Kf + (kbase + t0) * 16);
        const float4* vg = reinterpret_cast<const float4*>(g_V  + (kbase + t0) * 8);
#pragma unroll
        for (int i = 0; i < 4; i++) sK[threadIdx.x + i * QT] = kg[threadIdx.x + i * QT];
#pragma unroll
        for (int i = 0; i < 2; i++) sV[threadIdx.x + i * QT] = vg[threadIdx.x + i * QT];
        __syncthreads();

#pragma unroll 4
        for (int j = 0; j < TK; j++) {
            const float4 k0 = sK[j * 4 + 0];
            const float4 k1 = sK[j * 4 + 1];
            const float4 k2 = sK[j * 4 + 2];
            const float4 k3 = sK[j * 4 + 3];
            float d0 = q0.x * k0.x + q0.y * k0.y + q0.z * k0.z + q0.w * k0.w;
            float d1 = q1.x * k1.x + q1.y * k1.y + q1.z * k1.z + q1.w * k1.w;
            float d2 = q2.x * k2.x + q2.y * k2.y + q2.z * k2.z + q2.w * k2.w;
            float d3 = q3.x * k3.x + q3.y * k3.y + q3.z * k3.z + q3.w * k3.w;
            float sim = fabsf((d0 + d1) + (d2 + d3));
            float e = __expf(sim);
            den += e;
            const float4 v0 = sV[j * 2 + 0];
            const float4 v1 = sV[j * 2 + 1];
            a0 += e * v0.x; a1 += e * v0.y; a2 += e * v0.z; a3 += e * v0.w;
            a4 += e * v1.x; a5 += e * v1.y; a6 += e * v1.z; a7 += e * v1.w;
        }
        __syncthreads();
    }

    float* out = g_part + ((size_t)(b * SN + qi) * KSPLIT + ks) * 9;
    out[0] = den;
    out[1] = a0; out[2] = a1; out[3] = a2; out[4] = a3;
    out[5] = a4; out[6] = a5; out[7] = a6; out[8] = a7;
}

/* ---------------- Kernel 3: combine splits + output projection ---------------- */
__global__ void finalize_kernel(const float* __restrict__ W,
                                const float* __restrict__ bias,
                                float* __restrict__ out) {
    int t = blockIdx.x * blockDim.x + threadIdx.x;
    if (t >= NTOK) return;

    float den = 0.f, num[8];
#pragma unroll
    for (int e = 0; e < 8; e++) num[e] = 0.f;
#pragma unroll
    for (int ks = 0; ks < KSPLIT; ks++) {
        const float* p = g_part + ((size_t)t * KSPLIT + ks) * 9;
        den += p[0];
#pragma unroll
        for (int e = 0; e < 8; e++) num[e] += p[1 + e];
    }
    float inv = 1.0f / den;
    float o[8];
#pragma unroll
    for (int e = 0; e < 8; e++) o[e] = num[e] * inv;

#pragma unroll
    for (int d = 0; d < 8; d++) {
        float y = __ldg(&bias[d]);
#pragma unroll
        for (int e = 0; e < 8; e++) y += o[e] * __ldg(&W[d * 8 + e]);
        out[t * 8 + d] = y;
    }
}

extern "C" void kernel_launch(void* const* d_in, const int* in_sizes, int n_in,
                              void* d_out, int out_size) {
    const float* x     = (const float*)d_in[0];
    const float* phi_q = (const float*)d_in[1];
    const float* phi_k = (const float*)d_in[2];
    const float* phi_v = (const float*)d_in[3];
    const float* W     = (const float*)d_in[4];
    const float* bias  = (const float*)d_in[5];
    float* out = (float*)d_out;

    features_kernel<<<NTOK / 256, 256>>>(x, phi_q, phi_k, phi_v);

    dim3 grid(SN / QT, KSPLIT, BN);
    attn_partial_kernel<<<grid, QT>>>();

    finalize_kernel<<<NTOK / 256, 256>>>(W, bias, out);
}

// round 2
// speedup vs baseline: 1.1650x; 1.1650x over previous
#include <cuda_runtime.h>

#define BN 8
#define SN 2048
#define EN 8
#define NTOK (BN*SN)
#define KSPLIT 8
#define KCHUNK (SN/KSPLIT)   /* 256 keys per split */
#define TK 128               /* key tile in smem */
#define NTHR 128             /* threads per CTA; each thread owns 2 queries */
#define QPC 256              /* queries per CTA */

typedef unsigned long long u64;

/* Scratch (allocation-free rule: device globals) */
__device__ float g_Qf[NTOK * 16];
__device__ float g_Kf[NTOK * 16];
__device__ float g_V [NTOK * 8];
__device__ float g_den[NTOK * KSPLIT];
__device__ float g_num[(size_t)NTOK * KSPLIT * 8];

/* ---- packed f32x2 helpers (Blackwell FFMA2 via PTX) ---- */
__device__ __forceinline__ u64 fma2(u64 a, u64 b, u64 c) {
    u64 d;
    asm("fma.rn.f32x2 %0, %1, %2, %3;" : "=l"(d) : "l"(a), "l"(b), "l"(c));
    return d;
}
__device__ __forceinline__ u64 mul2(u64 a, u64 b) {
    u64 d;
    asm("mul.rn.f32x2 %0, %1, %2;" : "=l"(d) : "l"(a), "l"(b));
    return d;
}
__device__ __forceinline__ float2 unpack2(u64 d) {
    float2 r;
    asm("mov.b64 {%0, %1}, %2;" : "=f"(r.x), "=f"(r.y) : "l"(d));
    return r;
}
__device__ __forceinline__ u64 pack_dup(float e) {
    u64 d;
    asm("mov.b64 %0, {%1, %1};" : "=l"(d) : "f"(e));
    return d;
}

/* ---------------- Kernel 1: per-token features ----------------
 * qlayer(x, phi)_w = prod_{u<=w} cos(x_u+phi_u)  (w>=1),
 * qlayer_0 = prod_{u=1..7} cos(x_u+phi_u).
 * Similarity features: Phi[m] = prod_{w<4} (bit_w(m) ? sin(q_w/2) : cos(q_w/2)).
 */
__device__ __forceinline__ void qk_features(const float xv[8], const float ph[8],
                                            float out16[16]) {
    float c[8];
#pragma unroll
    for (int u = 0; u < 8; u++) c[u] = __cosf(xv[u] + ph[u]);
    float q1 = c[0] * c[1];
    float q2 = q1 * c[2];
    float q3 = q2 * c[3];
    float q0 = c[1] * c[2] * c[3] * c[4] * c[5] * c[6] * c[7];
    float s0, s1, s2, s3, a0, a1, a2, a3;
    __sincosf(0.5f * q0, &s0, &a0);
    __sincosf(0.5f * q1, &s1, &a1);
    __sincosf(0.5f * q2, &s2, &a2);
    __sincosf(0.5f * q3, &s3, &a3);
    float t01[4] = {a0 * a1, s0 * a1, a0 * s1, s0 * s1};
    float t23[4] = {a2 * a3, s2 * a3, a2 * s3, s2 * s3};
#pragma unroll
    for (int m = 0; m < 16; m++) out16[m] = t01[m & 3] * t23[m >> 2];
}

__global__ void features_kernel(const float* __restrict__ x,
                                const float* __restrict__ phi_q,
                                const float* __restrict__ phi_k,
                                const float* __restrict__ phi_v) {
    int t = blockIdx.x * blockDim.x + threadIdx.x;
    if (t >= NTOK) return;

    float xv[8];
    const float4* xp = reinterpret_cast<const float4*>(x + t * 8);
    float4 xa = xp[0], xb = xp[1];
    xv[0] = xa.x; xv[1] = xa.y; xv[2] = xa.z; xv[3] = xa.w;
    xv[4] = xb.x; xv[5] = xb.y; xv[6] = xb.z; xv[7] = xb.w;

    float pq[8], pk[8], pv[8];
#pragma unroll
    for (int u = 0; u < 8; u++) {
        pq[u] = __ldg(&phi_q[u]);
        pk[u] = __ldg(&phi_k[u]);
        pv[u] = __ldg(&phi_v[u]);
    }

    float fq[16], fk[16];
    qk_features(xv, pq, fq);
    qk_features(xv, pk, fk);

    float4* qo = reinterpret_cast<float4*>(g_Qf + t * 16);
    float4* ko = reinterpret_cast<float4*>(g_Kf + t * 16);
#pragma unroll
    for (int i = 0; i < 4; i++) {
        qo[i] = make_float4(fq[4 * i], fq[4 * i + 1], fq[4 * i + 2], fq[4 * i + 3]);
        ko[i] = make_float4(fk[4 * i], fk[4 * i + 1], fk[4 * i + 2], fk[4 * i + 3]);
    }

    /* V: all 8 qlayer outputs */
    {
        float c[8];
#pragma unroll
        for (int u = 0; u < 8; u++) c[u] = __cosf(xv[u] + pv[u]);
        float v[8];
        v[1] = c[0] * c[1];
#pragma unroll
        for (int w = 2; w < 8; w++) v[w] = v[w - 1] * c[w];
        v[0] = c[1] * c[2] * c[3] * c[4] * c[5] * c[6] * c[7];
        float4* vo = reinterpret_cast<float4*>(g_V + t * 8);
        vo[0] = make_float4(v[0], v[1], v[2], v[3]);
        vo[1] = make_float4(v[4], v[5], v[6], v[7]);
    }
}

/* ---------------- Kernel 2: fused attention partials ----------------
 * sim(i,j) = |Qf_i . Kf_j| in [0,1] -> softmax without max subtraction.
 * Each thread owns TWO query rows (amortizes LDS); all heavy math is
 * packed f32x2 (Blackwell FFMA2). Keys split across blockIdx.y (KSPLIT).
 */
__global__ __launch_bounds__(NTHR) void attn_partial_kernel() {
    __shared__ ulonglong2 sK[TK * 4];   /* 128 keys x 16 floats = 8KB */
    __shared__ ulonglong2 sV[TK * 2];   /* 128 keys x 8  floats = 4KB */

    const int b  = blockIdx.z;
    const int ks = blockIdx.y;
    const int qA = blockIdx.x * QPC + threadIdx.x;         /* query A */
    const int qB = qA + NTHR;                              /* query B */

    /* Q features, packed as 8 f32x2 each */
    u64 qa[8], qb[8];
    {
        const ulonglong2* pa = reinterpret_cast<const ulonglong2*>(g_Qf + (size_t)(b * SN + qA) * 16);
        const ulonglong2* pb = reinterpret_cast<const ulonglong2*>(g_Qf + (size_t)(b * SN + qB) * 16);
#pragma unroll
        for (int i = 0; i < 4; i++) {
            ulonglong2 ta = pa[i], tb = pb[i];
            qa[2 * i] = ta.x; qa[2 * i + 1] = ta.y;
            qb[2 * i] = tb.x; qb[2 * i + 1] = tb.y;
        }
    }

    float denA = 0.f, denB = 0.f;
    u64 accA[4], accB[4];
#pragma unroll
    for (int i = 0; i < 4; i++) { accA[i] = 0ull; accB[i] = 0ull; }

    const int kbase = b * SN + ks * KCHUNK;

    for (int t0 = 0; t0 < KCHUNK; t0 += TK) {
        const ulonglong2* kg = reinterpret_cast<const ulonglong2*>(g_Kf + (size_t)(kbase + t0) * 16);
        const ulonglong2* vg = reinterpret_cast<const ulonglong2*>(g_V  + (size_t)(kbase + t0) * 8);
#pragma unroll
        for (int i = 0; i < 4; i++) sK[threadIdx.x + i * NTHR] = kg[threadIdx.x + i * NTHR];
#pragma unroll
        for (int i = 0; i < 2; i++) sV[threadIdx.x + i * NTHR] = vg[threadIdx.x + i * NTHR];
        __syncthreads();

#pragma unroll 2
        for (int j = 0; j < TK; j++) {
            const ulonglong2 k0 = sK[j * 4 + 0];
            const ulonglong2 k1 = sK[j * 4 + 1];
            const ulonglong2 k2 = sK[j * 4 + 2];
            const ulonglong2 k3 = sK[j * 4 + 3];

            u64 da = mul2(qa[0], k0.x);
            u64 db = mul2(qb[0], k0.x);
            da = fma2(qa[1], k0.y, da);  db = fma2(qb[1], k0.y, db);
            da = fma2(qa[2], k1.x, da);  db = fma2(qb[2], k1.x, db);
            da = fma2(qa[3], k1.y, da);  db = fma2(qb[3], k1.y, db);
            da = fma2(qa[4], k2.x, da);  db = fma2(qb[4], k2.x, db);
            da = fma2(qa[5], k2.y, da);  db = fma2(qb[5], k2.y, db);
            da = fma2(qa[6], k3.x, da);  db = fma2(qb[6], k3.x, db);
            da = fma2(qa[7], k3.y, da);  db = fma2(qb[7], k3.y, db);

            float2 ua = unpack2(da);
            float2 ub = unpack2(db);
            float eA = __expf(fabsf(ua.x + ua.y));
            float eB = __expf(fabsf(ub.x + ub.y));
            denA += eA;
            denB += eB;

            const ulonglong2 v0 = sV[j * 2 + 0];
            const ulonglong2 v1 = sV[j * 2 + 1];
            u64 ea2 = pack_dup(eA);
            u64 eb2 = pack_dup(eB);
            accA[0] = fma2(ea2, v0.x, accA[0]);  accB[0] = fma2(eb2, v0.x, accB[0]);
            accA[1] = fma2(ea2, v0.y, accA[1]);  accB[1] = fma2(eb2, v0.y, accB[1]);
            accA[2] = fma2(ea2, v1.x, accA[2]);  accB[2] = fma2(eb2, v1.x, accB[2]);
            accA[3] = fma2(ea2, v1.y, accA[3]);  accB[3] = fma2(eb2, v1.y, accB[3]);
        }
        __syncthreads();
    }

    /* write partials */
    g_den[(size_t)(b * SN + qA) * KSPLIT + ks] = denA;
    g_den[(size_t)(b * SN + qB) * KSPLIT + ks] = denB;
    {
        float4* na = reinterpret_cast<float4*>(g_num + ((size_t)(b * SN + qA) * KSPLIT + ks) * 8);
        float4* nb = reinterpret_cast<float4*>(g_num + ((size_t)(b * SN + qB) * KSPLIT + ks) * 8);
        float2 a0 = unpack2(accA[0]), a1 = unpack2(accA[1]), a2 = unpack2(accA[2]), a3 = unpack2(accA[3]);
        float2 b0 = unpack2(accB[0]), b1 = unpack2(accB[1]), b2 = unpack2(accB[2]), b3 = unpack2(accB[3]);
        na[0] = make_float4(a0.x, a0.y, a1.x, a1.y);
        na[1] = make_float4(a2.x, a2.y, a3.x, a3.y);
        nb[0] = make_float4(b0.x, b0.y, b1.x, b1.y);
        nb[1] = make_float4(b2.x, b2.y, b3.x, b3.y);
    }
}

/* ---------------- Kernel 3: combine splits + output projection ---------------- */
__global__ void finalize_kernel(const float* __restrict__ W,
                                const float* __restrict__ bias,
                                float* __restrict__ out) {
    int t = blockIdx.x * blockDim.x + threadIdx.x;
    if (t >= NTOK) return;

    float den = 0.f, num[8];
#pragma unroll
    for (int e = 0; e < 8; e++) num[e] = 0.f;
#pragma unroll
    for (int ks = 0; ks < KSPLIT; ks++) {
        den += g_den[(size_t)t * KSPLIT + ks];
        const float4* p = reinterpret_cast<const float4*>(g_num + ((size_t)t * KSPLIT + ks) * 8);
        float4 p0 = p[0], p1 = p[1];
        num[0] += p0.x; num[1] += p0.y; num[2] += p0.z; num[3] += p0.w;
        num[4] += p1.x; num[5] += p1.y; num[6] += p1.z; num[7] += p1.w;
    }
    float inv = 1.0f / den;
    float o[8];
#pragma unroll
    for (int e = 0; e < 8; e++) o[e] = num[e] * inv;

#pragma unroll
    for (int d = 0; d < 8; d++) {
        float y = __ldg(&bias[d]);
#pragma unroll
        for (int e = 0; e < 8; e++) y += o[e] * __ldg(&W[d * 8 + e]);
        out[t * 8 + d] = y;
    }
}

extern "C" void kernel_launch(void* const* d_in, const int* in_sizes, int n_in,
                              void* d_out, int out_size) {
    const float* x     = (const float*)d_in[0];
    const float* phi_q = (const float*)d_in[1];
    const float* phi_k = (const float*)d_in[2];
    const float* phi_v = (const float*)d_in[3];
    const float* W     = (const float*)d_in[4];
    const float* bias  = (const float*)d_in[5];
    float* out = (float*)d_out;

    features_kernel<<<NTOK / 256, 256>>>(x, phi_q, phi_k, phi_v);

    dim3 grid(SN / QPC, KSPLIT, BN);
    attn_partial_kernel<<<grid, NTHR>>>();

    finalize_kernel<<<NTOK / 256, 256>>>(W, bias, out);
}

// round 3
// speedup vs baseline: 1.6822x; 1.4440x over previous
#include <cuda_runtime.h>

#define BN 8
#define SN 2048
#define EN 8
#define NTOK (BN*SN)
#define KSPLIT 8
#define KCHUNK (SN/KSPLIT)   /* 256 keys per split */
#define TK 128               /* keys per smem tile (64 key-pairs) */
#define NTHR 128             /* threads per CTA; each thread owns 2 queries */
#define QPC 256              /* queries per CTA */
#define LOG2E 1.4426950408889634f

typedef unsigned long long u64;

/* Scratch (allocation-free rule: device globals) */
__device__ float g_Qf[NTOK * 8];                    /* [tok][Fa0..3*log2e, Fb0..3] */
__device__ float g_Kf[NTOK * 8];                    /* pair-interleaved: [tok/2][comp][2] */
__device__ float g_V [NTOK * 8];                    /* pair-interleaved: [tok/2][comp][2] */
__device__ float g_den[NTOK * KSPLIT];
__device__ float g_num[(size_t)NTOK * KSPLIT * 8];

/* ---- packed f32x2 helpers (Blackwell FFMA2 via PTX) ---- */
__device__ __forceinline__ u64 fma2(u64 a, u64 b, u64 c) {
    u64 d;
    asm("fma.rn.f32x2 %0, %1, %2, %3;" : "=l"(d) : "l"(a), "l"(b), "l"(c));
    return d;
}
__device__ __forceinline__ u64 mul2(u64 a, u64 b) {
    u64 d;
    asm("mul.rn.f32x2 %0, %1, %2;" : "=l"(d) : "l"(a), "l"(b));
    return d;
}
__device__ __forceinline__ u64 add2(u64 a, u64 b) {
    u64 d;
    asm("add.rn.f32x2 %0, %1, %2;" : "=l"(d) : "l"(a), "l"(b));
    return d;
}
__device__ __forceinline__ float2 unpack2(u64 d) {
    float2 r;
    asm("mov.b64 {%0, %1}, %2;" : "=f"(r.x), "=f"(r.y) : "l"(d));
    return r;
}
__device__ __forceinline__ u64 pack2(float lo, float hi) {
    u64 d;
    asm("mov.b64 %0, {%1, %2};" : "=l"(d) : "f"(lo), "f"(hi));
    return d;
}
__device__ __forceinline__ u64 pack_dup(float e) {
    u64 d;
    asm("mov.b64 %0, {%1, %1};" : "=l"(d) : "f"(e));
    return d;
}
__device__ __forceinline__ float ex2(float x) {
    float y;
    asm("ex2.approx.ftz.f32 %0, %1;" : "=f"(y) : "f"(x));
    return y;
}

/* ---------------- Kernel 1: per-token features ----------------
 * qlayer(x, phi)_w = prod_{u<=w} cos(x_u+phi_u)  (w>=1),
 * qlayer_0 = prod_{u=1..7} cos(x_u+phi_u).
 * Factorized similarity features: sim-dot = (Fa_q.Fa_k)*(Fb_q.Fb_k),
 * Fa = (c0c1, s0c1, c0s1, s0s1), Fb = (c2c3, s2c3, c2s3, s2s3)
 * from half-angles of qlayer outputs 0..3.
 */
__device__ __forceinline__ void qk_features(const float xv[8], const float ph[8],
                                            float Fa[4], float Fb[4]) {
    float c[8];
#pragma unroll
    for (int u = 0; u < 8; u++) c[u] = __cosf(xv[u] + ph[u]);
    float q1 = c[0] * c[1];
    float q2 = q1 * c[2];
    float q3 = q2 * c[3];
    float q0 = c[1] * c[2] * c[3] * c[4] * c[5] * c[6] * c[7];
    float s0, s1, s2, s3, a0, a1, a2, a3;
    __sincosf(0.5f * q0, &s0, &a0);
    __sincosf(0.5f * q1, &s1, &a1);
    __sincosf(0.5f * q2, &s2, &a2);
    __sincosf(0.5f * q3, &s3, &a3);
    Fa[0] = a0 * a1; Fa[1] = s0 * a1; Fa[2] = a0 * s1; Fa[3] = s0 * s1;
    Fb[0] = a2 * a3; Fb[1] = s2 * a3; Fb[2] = a2 * s3; Fb[3] = s2 * s3;
}

__global__ void features_kernel(const float* __restrict__ x,
                                const float* __restrict__ phi_q,
                                const float* __restrict__ phi_k,
                                const float* __restrict__ phi_v) {
    int t = blockIdx.x * blockDim.x + threadIdx.x;
    if (t >= NTOK) return;

    float xv[8];
    const float4* xp = reinterpret_cast<const float4*>(x + t * 8);
    float4 xa = xp[0], xb = xp[1];
    xv[0] = xa.x; xv[1] = xa.y; xv[2] = xa.z; xv[3] = xa.w;
    xv[4] = xb.x; xv[5] = xb.y; xv[6] = xb.z; xv[7] = xb.w;

    float pq[8], pk[8], pv[8];
#pragma unroll
    for (int u = 0; u < 8; u++) {
        pq[u] = __ldg(&phi_q[u]);
        pk[u] = __ldg(&phi_k[u]);
        pv[u] = __ldg(&phi_v[u]);
    }

    float Fa[4], Fb[4];

    /* Q features: contiguous per token, Fa prescaled by log2e */
    qk_features(xv, pq, Fa, Fb);
    {
        float4* qo = reinterpret_cast<float4*>(g_Qf + (size_t)t * 8);
        qo[0] = make_float4(Fa[0] * LOG2E, Fa[1] * LOG2E, Fa[2] * LOG2E, Fa[3] * LOG2E);
        qo[1] = make_float4(Fb[0], Fb[1], Fb[2], Fb[3]);
    }

    /* K features: pair-interleaved layout [tok/2][comp][2] */
    qk_features(xv, pk, Fa, Fb);
    {
        float* ko = g_Kf + (size_t)(t & ~1) * 8 + (t & 1);
#pragma unroll
        for (int ccc = 0; ccc < 4; ccc++) ko[ccc * 2] = Fa[ccc];
#pragma unroll
        for (int ccc = 0; ccc < 4; ccc++) ko[(4 + ccc) * 2] = Fb[ccc];
    }

    /* V: all 8 qlayer outputs, pair-interleaved layout */
    {
        float c[8];
#pragma unroll
        for (int u = 0; u < 8; u++) c[u] = __cosf(xv[u] + pv[u]);
        float v[8];
        v[1] = c[0] * c[1];
#pragma unroll
        for (int w = 2; w < 8; w++) v[w] = v[w - 1] * c[w];
        v[0] = c[1] * c[2] * c[3] * c[4] * c[5] * c[6] * c[7];
        float* vo = g_V + (size_t)(t & ~1) * 8 + (t & 1);
#pragma unroll
        for (int ccc = 0; ccc < 8; ccc++) vo[ccc * 2] = v[ccc];
    }
}

/* ---------------- Kernel 2: fused attention partials ----------------
 * sim(i,j) = |(Fa_qi.Fa_kj)(Fb_qi.Fb_kj)| in [0,1] -> softmax w/o max-sub.
 * Packed f32x2 over KEY PAIRS: query comps dup'd, K/V pair-interleaved.
 * Each thread owns two query rows; keys split across blockIdx.y (KSPLIT).
 */
__global__ __launch_bounds__(NTHR) void attn_partial_kernel() {
    __shared__ u64 sK[TK / 2 * 8];   /* 64 key-pairs x 8 packed comps = 4KB */
    __shared__ u64 sV[TK / 2 * 8];   /* 64 key-pairs x 8 packed comps = 4KB */

    const int b  = blockIdx.z;
    const int ks = blockIdx.y;
    const int qA = blockIdx.x * QPC + threadIdx.x;   /* query A */
    const int qB = qA + NTHR;                        /* query B */

    /* Query features, each component dup'd into both f32x2 lanes */
    u64 qa[8], qb[8];
    {
        const float* pa = g_Qf + (size_t)(b * SN + qA) * 8;
        const float* pb = g_Qf + (size_t)(b * SN + qB) * 8;
#pragma unroll
        for (int i = 0; i < 8; i++) {
            qa[i] = pack_dup(pa[i]);
            qb[i] = pack_dup(pb[i]);
        }
    }

    u64 denA = 0ull, denB = 0ull;
    u64 accA[8], accB[8];
#pragma unroll
    for (int i = 0; i < 8; i++) { accA[i] = 0ull; accB[i] = 0ull; }

    const int kbase = b * SN + ks * KCHUNK;

    for (int t0 = 0; t0 < KCHUNK; t0 += TK) {
        /* K/V tiles contiguous in pair-interleaved layout: TK keys = TK/2*8 u64 */
        const u64* kg = reinterpret_cast<const u64*>(g_Kf + (size_t)(kbase + t0) * 8);
        const u64* vg = reinterpret_cast<const u64*>(g_V  + (size_t)(kbase + t0) * 8);
        const ulonglong2* kg2 = reinterpret_cast<const ulonglong2*>(kg);
        const ulonglong2* vg2 = reinterpret_cast<const ulonglong2*>(vg);
        ulonglong2* sK2 = reinterpret_cast<ulonglong2*>(sK);
        ulonglong2* sV2 = reinterpret_cast<ulonglong2*>(sV);
#pragma unroll
        for (int i = 0; i < 2; i++) sK2[threadIdx.x + i * NTHR] = kg2[threadIdx.x + i * NTHR];
#pragma unroll
        for (int i = 0; i < 2; i++) sV2[threadIdx.x + i * NTHR] = vg2[threadIdx.x + i * NTHR];
        __syncthreads();

#pragma unroll 2
        for (int jp = 0; jp < TK / 2; jp++) {
            const u64* kp = sK + jp * 8;
            const u64* vp = sV + jp * 8;
            u64 k0 = kp[0], k1 = kp[1], k2 = kp[2], k3 = kp[3];
            u64 k4 = kp[4], k5 = kp[5], k6 = kp[6], k7 = kp[7];

            /* factorized dot for both key lanes, both queries */
            u64 daA = mul2(qa[0], k0);
            u64 daB = mul2(qb[0], k0);
            daA = fma2(qa[1], k1, daA);  daB = fma2(qb[1], k1, daB);
            daA = fma2(qa[2], k2, daA);  daB = fma2(qb[2], k2, daB);
            daA = fma2(qa[3], k3, daA);  daB = fma2(qb[3], k3, daB);
            u64 dbA = mul2(qa[4], k4);
            u64 dbB = mul2(qb[4], k4);
            dbA = fma2(qa[5], k5, dbA);  dbB = fma2(qb[5], k5, dbB);
            dbA = fma2(qa[6], k6, dbA);  dbB = fma2(qb[6], k6, dbB);
            dbA = fma2(qa[7], k7, dbA);  dbB = fma2(qb[7], k7, dbB);
            u64 dA = mul2(daA, dbA);     /* (log2e*simA_k0, log2e*simA_k1) signed */
            u64 dB = mul2(daB, dbB);

            float2 uA = unpack2(dA);
            float2 uB = unpack2(dB);
            u64 eA2 = pack2(ex2(fabsf(uA.x)), ex2(fabsf(uA.y)));
            u64 eB2 = pack2(ex2(fabsf(uB.x)), ex2(fabsf(uB.y)));
            denA = add2(denA, eA2);
            denB = add2(denB, eB2);

#pragma unroll
            for (int ccc = 0; ccc < 8; ccc++) {
                u64 vc = vp[ccc];
                accA[ccc] = fma2(eA2, vc, accA[ccc]);
                accB[ccc] = fma2(eB2, vc, accB[ccc]);
            }
        }
        __syncthreads();
    }

    /* horizontal-add packed lanes, write partials */
    {
        float2 dA = unpack2(denA);
        float2 dB = unpack2(denB);
        g_den[(size_t)(b * SN + qA) * KSPLIT + ks] = dA.x + dA.y;
        g_den[(size_t)(b * SN + qB) * KSPLIT + ks] = dB.x + dB.y;
        float na[8], nb[8];
#pragma unroll
        for (int ccc = 0; ccc < 8; ccc++) {
            float2 a = unpack2(accA[ccc]);
            float2 bb = unpack2(accB[ccc]);
            na[ccc] = a.x + a.y;
            nb[ccc] = bb.x + bb.y;
        }
        float4* oa = reinterpret_cast<float4*>(g_num + ((size_t)(b * SN + qA) * KSPLIT + ks) * 8);
        float4* ob = reinterpret_cast<float4*>(g_num + ((size_t)(b * SN + qB) * KSPLIT + ks) * 8);
        oa[0] = make_float4(na[0], na[1], na[2], na[3]);
        oa[1] = make_float4(na[4], na[5], na[6], na[7]);
        ob[0] = make_float4(nb[0], nb[1], nb[2], nb[3]);
        ob[1] = make_float4(nb[4], nb[5], nb[6], nb[7]);
    }
}

/* ---------------- Kernel 3: combine splits + output projection ---------------- */
__global__ void finalize_kernel(const float* __restrict__ W,
                                const float* __restrict__ bias,
                                float* __restrict__ out) {
    int t = blockIdx.x * blockDim.x + threadIdx.x;
    if (t >= NTOK) return;

    float den = 0.f, num[8];
#pragma unroll
    for (int e = 0; e < 8; e++) num[e] = 0.f;
#pragma unroll
    for (int ks = 0; ks < KSPLIT; ks++) {
        den += g_den[(size_t)t * KSPLIT + ks];
        const float4* p = reinterpret_cast<const float4*>(g_num + ((size_t)t * KSPLIT + ks) * 8);
        float4 p0 = p[0], p1 = p[1];
        num[0] += p0.x; num[1] += p0.y; num[2] += p0.z; num[3] += p0.w;
        num[4] += p1.x; num[5] += p1.y; num[6] += p1.z; num[7] += p1.w;
    }
    float inv = 1.0f / den;
    float o[8];
#pragma unroll
    for (int e = 0; e < 8; e++) o[e] = num[e] * inv;

#pragma unroll
    for (int d = 0; d < 8; d++) {
        float y = __ldg(&bias[d]);
#pragma unroll
        for (int e = 0; e < 8; e++) y += o[e] * __ldg(&W[d * 8 + e]);
        out[t * 8 + d] = y;
    }
}

extern "C" void kernel_launch(void* const* d_in, const int* in_sizes, int n_in,
                              void* d_out, int out_size) {
    const float* x     = (const float*)d_in[0];
    const float* phi_q = (const float*)d_in[1];
    const float* phi_k = (const float*)d_in[2];
    const float* phi_v = (const float*)d_in[3];
    const float* W     = (const float*)d_in[4];
    const float* bias  = (const float*)d_in[5];
    float* out = (float*)d_out;

    features_kernel<<<NTOK / 128, 128>>>(x, phi_q, phi_k, phi_v);

    dim3 grid(SN / QPC, KSPLIT, BN);
    attn_partial_kernel<<<grid, NTHR>>>();

    finalize_kernel<<<NTOK / 256, 256>>>(W, bias, out);
}

// round 4
// speedup vs baseline: 1.6953x; 1.0078x over previous
#include <cuda_runtime.h>

#define BN 8
#define SN 2048
#define EN 8
#define NTOK (BN*SN)
#define KSPLIT 16
#define KCHUNK (SN/KSPLIT)   /* 128 keys per split == one smem tile */
#define TK 128               /* keys per smem tile (64 key-pairs) */
#define NTHR 128             /* threads per CTA; each thread owns 2 queries */
#define QPC 256              /* queries per CTA */
#define LOG2E 1.4426950408889634f

typedef unsigned long long u64;

/* Scratch (allocation-free rule: device globals) */
__device__ float g_Qf[NTOK * 8];                    /* [tok][Fa0..3*log2e, Fb0..3] */
__device__ float g_Kf[NTOK * 8];                    /* pair-interleaved: [tok/2][comp][2] */
__device__ float g_V [NTOK * 8];                    /* pair-interleaved: [tok/2][comp][2] */
__device__ float g_den[NTOK * KSPLIT];
__device__ float g_num[(size_t)NTOK * KSPLIT * 8];

/* ---- packed f32x2 helpers (Blackwell FFMA2 via PTX) ---- */
__device__ __forceinline__ u64 fma2(u64 a, u64 b, u64 c) {
    u64 d;
    asm("fma.rn.f32x2 %0, %1, %2, %3;" : "=l"(d) : "l"(a), "l"(b), "l"(c));
    return d;
}
__device__ __forceinline__ u64 mul2(u64 a, u64 b) {
    u64 d;
    asm("mul.rn.f32x2 %0, %1, %2;" : "=l"(d) : "l"(a), "l"(b));
    return d;
}
__device__ __forceinline__ u64 add2(u64 a, u64 b) {
    u64 d;
    asm("add.rn.f32x2 %0, %1, %2;" : "=l"(d) : "l"(a), "l"(b));
    return d;
}
__device__ __forceinline__ float2 unpack2(u64 d) {
    float2 r;
    asm("mov.b64 {%0, %1}, %2;" : "=f"(r.x), "=f"(r.y) : "l"(d));
    return r;
}
__device__ __forceinline__ u64 pack2(float lo, float hi) {
    u64 d;
    asm("mov.b64 %0, {%1, %2};" : "=l"(d) : "f"(lo), "f"(hi));
    return d;
}
__device__ __forceinline__ u64 pack_dup(float e) {
    u64 d;
    asm("mov.b64 %0, {%1, %1};" : "=l"(d) : "f"(e));
    return d;
}
__device__ __forceinline__ float ex2(float x) {
    float y;
    asm("ex2.approx.ftz.f32 %0, %1;" : "=f"(y) : "f"(x));
    return y;
}

/* ---------------- Kernel 1: per-token features ----------------
 * 3-way parallel over blockIdx.y = {0:Q, 1:K, 2:V}.
 * qlayer(x, phi)_w = prod_{u<=w} cos(x_u+phi_u)  (w>=1),
 * qlayer_0 = prod_{u=1..7} cos(x_u+phi_u).
 * Factorized similarity features: sim-dot = (Fa_q.Fa_k)*(Fb_q.Fb_k).
 */
__device__ __forceinline__ void qk_features(const float xv[8], const float* __restrict__ ph,
                                            float Fa[4], float Fb[4]) {
    float c[8];
#pragma unroll
    for (int u = 0; u < 8; u++) c[u] = __cosf(xv[u] + __ldg(&ph[u]));
    float q1 = c[0] * c[1];
    float q2 = q1 * c[2];
    float q3 = q2 * c[3];
    float q0 = c[1] * c[2] * c[3] * c[4] * c[5] * c[6] * c[7];
    float s0, s1, s2, s3, a0, a1, a2, a3;
    __sincosf(0.5f * q0, &s0, &a0);
    __sincosf(0.5f * q1, &s1, &a1);
    __sincosf(0.5f * q2, &s2, &a2);
    __sincosf(0.5f * q3, &s3, &a3);
    Fa[0] = a0 * a1; Fa[1] = s0 * a1; Fa[2] = a0 * s1; Fa[3] = s0 * s1;
    Fb[0] = a2 * a3; Fb[1] = s2 * a3; Fb[2] = a2 * s3; Fb[3] = s2 * s3;
}

__global__ void features_kernel(const float* __restrict__ x,
                                const float* __restrict__ phi_q,
                                const float* __restrict__ phi_k,
                                const float* __restrict__ phi_v) {
    int t = blockIdx.x * blockDim.x + threadIdx.x;
    if (t >= NTOK) return;
    const int kind = blockIdx.y;

    float xv[8];
    const float4* xp = reinterpret_cast<const float4*>(x + (size_t)t * 8);
    float4 xa = xp[0], xb = xp[1];
    xv[0] = xa.x; xv[1] = xa.y; xv[2] = xa.z; xv[3] = xa.w;
    xv[4] = xb.x; xv[5] = xb.y; xv[6] = xb.z; xv[7] = xb.w;

    if (kind == 0) {
        /* Q features: contiguous per token, Fa prescaled by log2e */
        float Fa[4], Fb[4];
        qk_features(xv, phi_q, Fa, Fb);
        float4* qo = reinterpret_cast<float4*>(g_Qf + (size_t)t * 8);
        qo[0] = make_float4(Fa[0] * LOG2E, Fa[1] * LOG2E, Fa[2] * LOG2E, Fa[3] * LOG2E);
        qo[1] = make_float4(Fb[0], Fb[1], Fb[2], Fb[3]);
    } else if (kind == 1) {
        /* K features: pair-interleaved layout [tok/2][comp][2] */
        float Fa[4], Fb[4];
        qk_features(xv, phi_k, Fa, Fb);
        float* ko = g_Kf + (size_t)(t & ~1) * 8 + (t & 1);
#pragma unroll
        for (int ccc = 0; ccc < 4; ccc++) ko[ccc * 2] = Fa[ccc];
#pragma unroll
        for (int ccc = 0; ccc < 4; ccc++) ko[(4 + ccc) * 2] = Fb[ccc];
    } else {
        /* V: all 8 qlayer outputs, pair-interleaved layout */
        float c[8];
#pragma unroll
        for (int u = 0; u < 8; u++) c[u] = __cosf(xv[u] + __ldg(&phi_v[u]));
        float v[8];
        v[1] = c[0] * c[1];
#pragma unroll
        for (int w = 2; w < 8; w++) v[w] = v[w - 1] * c[w];
        v[0] = c[1] * c[2] * c[3] * c[4] * c[5] * c[6] * c[7];
        float* vo = g_V + (size_t)(t & ~1) * 8 + (t & 1);
#pragma unroll
        for (int ccc = 0; ccc < 8; ccc++) vo[ccc * 2] = v[ccc];
    }
}

/* ---------------- Kernel 2: fused attention partials ----------------
 * sim(i,j) = |(Fa_qi.Fa_kj)(Fb_qi.Fb_kj)| in [0,1] -> softmax w/o max-sub.
 * Packed f32x2 over KEY PAIRS. Each thread owns two query rows; each CTA
 * owns one 128-key chunk (KSPLIT=16) -> single smem tile, no k-loop.
 */
__global__ __launch_bounds__(NTHR) void attn_partial_kernel() {
    __shared__ u64 sK[TK / 2 * 8];   /* 64 key-pairs x 8 packed comps = 4KB */
    __shared__ u64 sV[TK / 2 * 8];   /* 64 key-pairs x 8 packed comps = 4KB */

    const int b  = blockIdx.z;
    const int ks = blockIdx.y;
    const int qA = blockIdx.x * QPC + threadIdx.x;   /* query A */
    const int qB = qA + NTHR;                        /* query B */

    /* fill the single K/V tile */
    {
        const int kbase = b * SN + ks * KCHUNK;
        const ulonglong2* kg2 = reinterpret_cast<const ulonglong2*>(g_Kf + (size_t)kbase * 8);
        const ulonglong2* vg2 = reinterpret_cast<const ulonglong2*>(g_V  + (size_t)kbase * 8);
        ulonglong2* sK2 = reinterpret_cast<ulonglong2*>(sK);
        ulonglong2* sV2 = reinterpret_cast<ulonglong2*>(sV);
#pragma unroll
        for (int i = 0; i < 2; i++) sK2[threadIdx.x + i * NTHR] = kg2[threadIdx.x + i * NTHR];
#pragma unroll
        for (int i = 0; i < 2; i++) sV2[threadIdx.x + i * NTHR] = vg2[threadIdx.x + i * NTHR];
    }

    /* Query features, each component dup'd into both f32x2 lanes */
    u64 qa[8], qb[8];
    {
        const float* pa = g_Qf + (size_t)(b * SN + qA) * 8;
        const float* pb = g_Qf + (size_t)(b * SN + qB) * 8;
#pragma unroll
        for (int i = 0; i < 8; i++) {
            qa[i] = pack_dup(pa[i]);
            qb[i] = pack_dup(pb[i]);
        }
    }

    u64 denA = 0ull, denB = 0ull;
    u64 accA[8], accB[8];
#pragma unroll
    for (int i = 0; i < 8; i++) { accA[i] = 0ull; accB[i] = 0ull; }

    __syncthreads();

#pragma unroll 4
    for (int jp = 0; jp < TK / 2; jp++) {
        const u64* kp = sK + jp * 8;
        const u64* vp = sV + jp * 8;
        u64 k0 = kp[0], k1 = kp[1], k2 = kp[2], k3 = kp[3];
        u64 k4 = kp[4], k5 = kp[5], k6 = kp[6], k7 = kp[7];

        /* factorized dot for both key lanes, both queries */
        u64 daA = mul2(qa[0], k0);
        u64 daB = mul2(qb[0], k0);
        daA = fma2(qa[1], k1, daA);  daB = fma2(qb[1], k1, daB);
        daA = fma2(qa[2], k2, daA);  daB = fma2(qb[2], k2, daB);
        daA = fma2(qa[3], k3, daA);  daB = fma2(qb[3], k3, daB);
        u64 dbA = mul2(qa[4], k4);
        u64 dbB = mul2(qb[4], k4);
        dbA = fma2(qa[5], k5, dbA);  dbB = fma2(qb[5], k5, dbB);
        dbA = fma2(qa[6], k6, dbA);  dbB = fma2(qb[6], k6, dbB);
        dbA = fma2(qa[7], k7, dbA);  dbB = fma2(qb[7], k7, dbB);
        u64 dA = mul2(daA, dbA);     /* (log2e*simA_k0, log2e*simA_k1) signed */
        u64 dB = mul2(daB, dbB);

        float2 uA = unpack2(dA);
        float2 uB = unpack2(dB);
        u64 eA2 = pack2(ex2(fabsf(uA.x)), ex2(fabsf(uA.y)));
        u64 eB2 = pack2(ex2(fabsf(uB.x)), ex2(fabsf(uB.y)));
        denA = add2(denA, eA2);
        denB = add2(denB, eB2);

#pragma unroll
        for (int ccc = 0; ccc < 8; ccc++) {
            u64 vc = vp[ccc];
            accA[ccc] = fma2(eA2, vc, accA[ccc]);
            accB[ccc] = fma2(eB2, vc, accB[ccc]);
        }
    }

    /* horizontal-add packed lanes, write partials */
    {
        float2 dA = unpack2(denA);
        float2 dB = unpack2(denB);
        g_den[(size_t)(b * SN + qA) * KSPLIT + ks] = dA.x + dA.y;
        g_den[(size_t)(b * SN + qB) * KSPLIT + ks] = dB.x + dB.y;
        float na[8], nb[8];
#pragma unroll
        for (int ccc = 0; ccc < 8; ccc++) {
            float2 a = unpack2(accA[ccc]);
            float2 bb = unpack2(accB[ccc]);
            na[ccc] = a.x + a.y;
            nb[ccc] = bb.x + bb.y;
        }
        float4* oa = reinterpret_cast<float4*>(g_num + ((size_t)(b * SN + qA) * KSPLIT + ks) * 8);
        float4* ob = reinterpret_cast<float4*>(g_num + ((size_t)(b * SN + qB) * KSPLIT + ks) * 8);
        oa[0] = make_float4(na[0], na[1], na[2], na[3]);
        oa[1] = make_float4(na[4], na[5], na[6], na[7]);
        ob[0] = make_float4(nb[0], nb[1], nb[2], nb[3]);
        ob[1] = make_float4(nb[4], nb[5], nb[6], nb[7]);
    }
}

/* ---------------- Kernel 3: combine splits + output projection ---------------- */
__global__ void finalize_kernel(const float* __restrict__ W,
                                const float* __restrict__ bias,
                                float* __restrict__ out) {
    int t = blockIdx.x * blockDim.x + threadIdx.x;
    if (t >= NTOK) return;

    float den = 0.f, num[8];
#pragma unroll
    for (int e = 0; e < 8; e++) num[e] = 0.f;
#pragma unroll
    for (int ks = 0; ks < KSPLIT; ks++) {
        den += g_den[(size_t)t * KSPLIT + ks];
        const float4* p = reinterpret_cast<const float4*>(g_num + ((size_t)t * KSPLIT + ks) * 8);
        float4 p0 = p[0], p1 = p[1];
        num[0] += p0.x; num[1] += p0.y; num[2] += p0.z; num[3] += p0.w;
        num[4] += p1.x; num[5] += p1.y; num[6] += p1.z; num[7] += p1.w;
    }
    float inv = 1.0f / den;
    float o[8];
#pragma unroll
    for (int e = 0; e < 8; e++) o[e] = num[e] * inv;

#pragma unroll
    for (int d = 0; d < 8; d++) {
        float y = __ldg(&bias[d]);
#pragma unroll
        for (int e = 0; e < 8; e++) y += o[e] * __ldg(&W[d * 8 + e]);
        out[t * 8 + d] = y;
    }
}

extern "C" void kernel_launch(void* const* d_in, const int* in_sizes, int n_in,
                              void* d_out, int out_size) {
    const float* x     = (const float*)d_in[0];
    const float* phi_q = (const float*)d_in[1];
    const float* phi_k = (const float*)d_in[2];
    const float* phi_v = (const float*)d_in[3];
    const float* W     = (const float*)d_in[4];
    const float* bias  = (const float*)d_in[5];
    float* out = (float*)d_out;

    dim3 fgrid(NTOK / 256, 3);
    features_kernel<<<fgrid, 256>>>(x, phi_q, phi_k, phi_v);

    dim3 grid(SN / QPC, KSPLIT, BN);
    attn_partial_kernel<<<grid, NTHR>>>();

    finalize_kernel<<<NTOK / 256, 256>>>(W, bias, out);
}